// round 4
// baseline (speedup 1.0000x reference)
#include <cuda_runtime.h>
#include <math.h>

// Problem constants
#define BB 512   // batch
#define TT 256   // seq len
#define HH 256   // hidden
#define GG 1024  // 4*H gates
#define PP 14    // predict dim

#define BC 4                  // batch per CTA
#define NCTA (BB / BC)        // 128 CTAs
#define NT  256               // threads per CTA (one per hidden unit)

// ---------------- scratch (device globals; allocation-free) ----------------
// Layer-1 recurrent weights, transposed+gate-packed:
//   g_w1[(k*HH + h)*4 + q] = w_hh0[(q*HH + h)*HH + k]   (q: 0=i,1=f,2=g,3=o)
__device__ float g_w1[HH * HH * 4];
// Layer-2 weights (input + recurrent interleaved):
//   g_w2[((k*HH + h)*2 + m)*4 + q], m=0 -> w_ih1, m=1 -> w_hh1
__device__ float g_w2[HH * HH * 8];
// Packed biases/input weight: [h*4 + q]
__device__ float g_b0p[HH * 4];
__device__ float g_b1p[HH * 4];
__device__ float g_wxp[HH * 4];

// ---------------- prep: transpose + pack (runs each graph replay) ----------
__global__ void prep_kernel(const float* __restrict__ w_ih0,
                            const float* __restrict__ w_hh0,
                            const float* __restrict__ b_ih0,
                            const float* __restrict__ b_hh0,
                            const float* __restrict__ w_ih1,
                            const float* __restrict__ w_hh1,
                            const float* __restrict__ b_ih1,
                            const float* __restrict__ b_hh1)
{
    int tid = blockIdx.x * blockDim.x + threadIdx.x;
    int nthr = gridDim.x * blockDim.x;
    // pack big matrices: output-coalesced, scattered reads (one-time cost)
    for (int i = tid; i < HH * HH * 4; i += nthr) {
        int q = i & 3;
        int h = (i >> 2) & (HH - 1);
        int k = i >> 10;                 // i / (HH*4)
        int src = (q * HH + h) * HH + k; // row-major [4H, H]
        g_w1[i] = w_hh0[src];
        g_w2[(((long)(k * HH + h)) * 2 + 0) * 4 + q] = w_ih1[src];
        g_w2[(((long)(k * HH + h)) * 2 + 1) * 4 + q] = w_hh1[src];
    }
    for (int i = tid; i < HH * 4; i += nthr) {
        int q = i & 3;
        int h = i >> 2;
        int g = q * HH + h;
        g_b0p[i] = b_ih0[g] + b_hh0[g];
        g_b1p[i] = b_ih1[g] + b_hh1[g];
        g_wxp[i] = w_ih0[g];             // w_ih0 is [4H, 1]
    }
}

// ---------------- fused 2-layer LSTM + head ---------------------------------
__device__ __forceinline__ float sigf(float x) {
    return 1.0f / (1.0f + __expf(-x));
}

__global__ __launch_bounds__(NT, 1)
void lstm_kernel(const float* __restrict__ x,      // [B, T, 1]
                 const float* __restrict__ w_lin,  // [P, H]
                 const float* __restrict__ b_lin,  // [P]
                 float* __restrict__ out)          // [B, P]
{
    __shared__ float sH1[HH][BC];     // h1 state, [k][b] for float4 broadcast
    __shared__ float sH2[HH][BC];     // h2 state
    __shared__ float sx[BC][TT];      // input slice
    __shared__ float4 sWX[HH];        // packed w_ih0
    __shared__ float4 sB0[HH];        // packed bias layer 1
    __shared__ float4 sB1[HH];        // packed bias layer 2

    const int tid = threadIdx.x;
    const int b0  = blockIdx.x * BC;

    // preload per-CTA constants
    for (int i = tid; i < BC * TT; i += NT)
        sx[i / TT][i % TT] = x[(b0 + i / TT) * TT + (i % TT)];
    {
        const float4* wxp = reinterpret_cast<const float4*>(g_wxp);
        const float4* b0p = reinterpret_cast<const float4*>(g_b0p);
        const float4* b1p = reinterpret_cast<const float4*>(g_b1p);
        sWX[tid] = wxp[tid];
        sB0[tid] = b0p[tid];
        sB1[tid] = b1p[tid];
    }
    // init state
    float c1[BC], c2[BC];
#pragma unroll
    for (int b = 0; b < BC; ++b) { c1[b] = 0.f; c2[b] = 0.f; }
    *reinterpret_cast<float4*>(&sH1[tid][0]) = make_float4(0.f, 0.f, 0.f, 0.f);
    *reinterpret_cast<float4*>(&sH2[tid][0]) = make_float4(0.f, 0.f, 0.f, 0.f);
    __syncthreads();

    const float4* __restrict__ w1v = reinterpret_cast<const float4*>(g_w1);
    const float4* __restrict__ w2v = reinterpret_cast<const float4*>(g_w2);

    float ai[BC], af[BC], ag[BC], ao[BC];

    for (int t = 0; t < TT; ++t) {
        // ---------------- layer 1: gates for hidden unit `tid`
        {
            float4 wx = sWX[tid], bz = sB0[tid];
#pragma unroll
            for (int b = 0; b < BC; ++b) {
                float xv = sx[b][t];
                ai[b] = fmaf(xv, wx.x, bz.x);
                af[b] = fmaf(xv, wx.y, bz.y);
                ag[b] = fmaf(xv, wx.z, bz.z);
                ao[b] = fmaf(xv, wx.w, bz.w);
            }
        }
#pragma unroll 4
        for (int k = 0; k < HH; ++k) {
            float4 w  = w1v[k * HH + tid];                              // gates i,f,g,o
            float4 hv = *reinterpret_cast<const float4*>(&sH1[k][0]);   // batches 0..3
            ai[0] += hv.x * w.x; af[0] += hv.x * w.y; ag[0] += hv.x * w.z; ao[0] += hv.x * w.w;
            ai[1] += hv.y * w.x; af[1] += hv.y * w.y; ag[1] += hv.y * w.z; ao[1] += hv.y * w.w;
            ai[2] += hv.z * w.x; af[2] += hv.z * w.y; ag[2] += hv.z * w.z; ao[2] += hv.z * w.w;
            ai[3] += hv.w * w.x; af[3] += hv.w * w.y; ag[3] += hv.w * w.z; ao[3] += hv.w * w.w;
        }
        float h1n[BC];
#pragma unroll
        for (int b = 0; b < BC; ++b) {
            float I = sigf(ai[b]), F = sigf(af[b]);
            float Gv = tanhf(ag[b]), O = sigf(ao[b]);
            c1[b] = F * c1[b] + I * Gv;
            h1n[b] = O * tanhf(c1[b]);
        }
        __syncthreads();  // all reads of old h1 done
        *reinterpret_cast<float4*>(&sH1[tid][0]) =
            make_float4(h1n[0], h1n[1], h1n[2], h1n[3]);
        __syncthreads();

        // ---------------- layer 2: input (new h1) + recurrent (h2)
        {
            float4 bz = sB1[tid];
#pragma unroll
            for (int b = 0; b < BC; ++b) {
                ai[b] = (b == 0) ? bz.x : bz.x;  // keep simple: set below
            }
            ai[0] = bz.x; af[0] = bz.y; ag[0] = bz.z; ao[0] = bz.w;
            ai[1] = bz.x; af[1] = bz.y; ag[1] = bz.z; ao[1] = bz.w;
            ai[2] = bz.x; af[2] = bz.y; ag[2] = bz.z; ao[2] = bz.w;
            ai[3] = bz.x; af[3] = bz.y; ag[3] = bz.z; ao[3] = bz.w;
        }
#pragma unroll 2
        for (int k = 0; k < HH; ++k) {
            float4 wA = w2v[(k * HH + tid) * 2 + 0];   // w_ih1 gates
            float4 wB = w2v[(k * HH + tid) * 2 + 1];   // w_hh1 gates
            float4 h1v = *reinterpret_cast<const float4*>(&sH1[k][0]);
            float4 h2v = *reinterpret_cast<const float4*>(&sH2[k][0]);
            ai[0] += h1v.x * wA.x + h2v.x * wB.x;
            af[0] += h1v.x * wA.y + h2v.x * wB.y;
            ag[0] += h1v.x * wA.z + h2v.x * wB.z;
            ao[0] += h1v.x * wA.w + h2v.x * wB.w;
            ai[1] += h1v.y * wA.x + h2v.y * wB.x;
            af[1] += h1v.y * wA.y + h2v.y * wB.y;
            ag[1] += h1v.y * wA.z + h2v.y * wB.z;
            ao[1] += h1v.y * wA.w + h2v.y * wB.w;
            ai[2] += h1v.z * wA.x + h2v.z * wB.x;
            af[2] += h1v.z * wA.y + h2v.z * wB.y;
            ag[2] += h1v.z * wA.z + h2v.z * wB.z;
            ao[2] += h1v.z * wA.w + h2v.z * wB.w;
            ai[3] += h1v.w * wA.x + h2v.w * wB.x;
            af[3] += h1v.w * wA.y + h2v.w * wB.y;
            ag[3] += h1v.w * wA.z + h2v.w * wB.z;
            ao[3] += h1v.w * wA.w + h2v.w * wB.w;
        }
        float h2n[BC];
#pragma unroll
        for (int b = 0; b < BC; ++b) {
            float I = sigf(ai[b]), F = sigf(af[b]);
            float Gv = tanhf(ag[b]), O = sigf(ao[b]);
            c2[b] = F * c2[b] + I * Gv;
            h2n[b] = O * tanhf(c2[b]);
        }
        __syncthreads();  // all reads of old h2 done
        *reinterpret_cast<float4*>(&sH2[tid][0]) =
            make_float4(h2n[0], h2n[1], h2n[2], h2n[3]);
        __syncthreads();
    }

    // ---------------- linear head on final h2 (56 dot products per CTA)
    const int warp = tid >> 5, lane = tid & 31;
    for (int pair = warp; pair < BC * PP; pair += NT / 32) {
        int b = pair / PP, p = pair % PP;
        float s = 0.f;
        for (int k = lane; k < HH; k += 32)
            s += sH2[k][b] * w_lin[p * HH + k];
#pragma unroll
        for (int off = 16; off > 0; off >>= 1)
            s += __shfl_xor_sync(0xffffffff, s, off);
        if (lane == 0)
            out[(b0 + b) * PP + p] = s + b_lin[p];
    }
}

// ---------------- launch --------------------------------------------------
extern "C" void kernel_launch(void* const* d_in, const int* in_sizes, int n_in,
                              void* d_out, int out_size)
{
    const float* x     = (const float*)d_in[0];
    const float* w_ih0 = (const float*)d_in[1];
    const float* w_hh0 = (const float*)d_in[2];
    const float* b_ih0 = (const float*)d_in[3];
    const float* b_hh0 = (const float*)d_in[4];
    const float* w_ih1 = (const float*)d_in[5];
    const float* w_hh1 = (const float*)d_in[6];
    const float* b_ih1 = (const float*)d_in[7];
    const float* b_hh1 = (const float*)d_in[8];
    const float* w_lin = (const float*)d_in[9];
    const float* b_lin = (const float*)d_in[10];
    float* out = (float*)d_out;

    prep_kernel<<<256, 256>>>(w_ih0, w_hh0, b_ih0, b_hh0,
                              w_ih1, w_hh1, b_ih1, b_hh1);
    lstm_kernel<<<NCTA, NT>>>(x, w_lin, b_lin, out);
}

// round 5
// speedup vs baseline: 1.4612x; 1.4612x over previous
#include <cuda_runtime.h>
#include <math.h>

typedef unsigned long long u64;

// Problem constants
#define BB 512   // batch
#define TT 256   // seq len
#define HH 256   // hidden
#define PP 14    // predict dim

#define BC 4                  // batch per CTA
#define NCTA (BB / BC)        // 128 CTAs
#define NT  256               // threads per CTA (one per hidden unit)

// ---------------- scratch (device globals; allocation-free) ----------------
// Layer-1 recurrent weights, transposed+gate-packed:
//   g_w1[(k*HH + h)*4 + q] = w_hh0[(q*HH + h)*HH + k]   (q: 0=i,1=f,2=g,3=o)
__device__ __align__(16) float g_w1[HH * HH * 4];
// Layer-2 weights (input + recurrent interleaved):
//   g_w2[((k*HH + h)*2 + m)*4 + q], m=0 -> w_ih1, m=1 -> w_hh1
__device__ __align__(16) float g_w2[HH * HH * 8];
// Packed biases/input weight: [h*4 + q]
__device__ __align__(16) float g_b0p[HH * 4];
__device__ __align__(16) float g_b1p[HH * 4];
__device__ __align__(16) float g_wxp[HH * 4];

// ---------------- prep: transpose + pack --------------------------------
__global__ void prep_kernel(const float* __restrict__ w_ih0,
                            const float* __restrict__ w_hh0,
                            const float* __restrict__ b_ih0,
                            const float* __restrict__ b_hh0,
                            const float* __restrict__ w_ih1,
                            const float* __restrict__ w_hh1,
                            const float* __restrict__ b_ih1,
                            const float* __restrict__ b_hh1)
{
    int tid = blockIdx.x * blockDim.x + threadIdx.x;
    int nthr = gridDim.x * blockDim.x;
    for (int i = tid; i < HH * HH * 4; i += nthr) {
        int q = i & 3;
        int h = (i >> 2) & (HH - 1);
        int k = i >> 10;                 // i / (HH*4)
        int src = (q * HH + h) * HH + k; // row-major [4H, H]
        g_w1[i] = w_hh0[src];
        g_w2[((k * HH + h) * 2 + 0) * 4 + q] = w_ih1[src];
        g_w2[((k * HH + h) * 2 + 1) * 4 + q] = w_hh1[src];
    }
    for (int i = tid; i < HH * 4; i += nthr) {
        int q = i & 3;
        int h = i >> 2;
        int g = q * HH + h;
        g_b0p[i] = b_ih0[g] + b_hh0[g];
        g_b1p[i] = b_ih1[g] + b_hh1[g];
        g_wxp[i] = w_ih0[g];
    }
}

// ---------------- f32x2 helpers (Blackwell packed fp32 FMA) ---------------
__device__ __forceinline__ u64 pack2(float lo, float hi) {
    u64 r;
    asm("mov.b64 %0, {%1, %2};" : "=l"(r) : "f"(lo), "f"(hi));
    return r;
}
__device__ __forceinline__ u64 bc2(float v) { return pack2(v, v); }
__device__ __forceinline__ void up2(u64 v, float& lo, float& hi) {
    asm("mov.b64 {%0, %1}, %2;" : "=f"(lo), "=f"(hi) : "l"(v));
}
// d = a*b + d (two fp32 lanes per instruction)
__device__ __forceinline__ void fma2(u64& d, u64 a, u64 b) {
    asm("fma.rn.f32x2 %0, %1, %2, %0;" : "+l"(d) : "l"(a), "l"(b));
}

// fast, accurate nonlinearities (ex2.approx + rcp.approx ~1e-6 rel)
__device__ __forceinline__ float sigf(float x) {
    return __fdividef(1.0f, 1.0f + __expf(-x));
}
__device__ __forceinline__ float tanhfast(float x) {
    float e = __expf(2.0f * x);
    return 1.0f - __fdividef(2.0f, e + 1.0f);
}

// ---------------- fused 2-layer LSTM + head -------------------------------
__global__ __launch_bounds__(NT, 1)
void lstm_kernel(const float* __restrict__ x,      // [B, T, 1]
                 const float* __restrict__ w_lin,  // [P, H]
                 const float* __restrict__ b_lin,  // [P]
                 float* __restrict__ out)          // [B, P]
{
    // h state stored pre-duplicated: sH*[buf][k][j] holds
    //   j=0: (h_b0,h_b0),(h_b1,h_b1)   j=1: (h_b2,h_b2),(h_b3,h_b3)
    __shared__ ulonglong2 sH1[2][HH][2];
    __shared__ ulonglong2 sH2[2][HH][2];
    __shared__ float sx[BC][TT];

    const int tid = threadIdx.x;
    const int b0  = blockIdx.x * BC;

    for (int i = tid; i < BC * TT; i += NT)
        sx[i / TT][i % TT] = x[(b0 + i / TT) * TT + (i % TT)];

    // per-thread constants (registers only)
    float4 wx  = ((const float4*)g_wxp)[tid];
    float4 bz0 = ((const float4*)g_b0p)[tid];
    float4 bz1 = ((const float4*)g_b1p)[tid];
    const u64 wx_if = pack2(wx.x, wx.y),  wx_go = pack2(wx.z, wx.w);
    const u64 b0_if = pack2(bz0.x, bz0.y), b0_go = pack2(bz0.z, bz0.w);
    const u64 b1_if = pack2(bz1.x, bz1.y), b1_go = pack2(bz1.z, bz1.w);

    float c1[BC], c2[BC];
#pragma unroll
    for (int b = 0; b < BC; ++b) { c1[b] = 0.f; c2[b] = 0.f; }
    {
        ulonglong2 z; z.x = 0ull; z.y = 0ull;
        sH1[0][tid][0] = z; sH1[0][tid][1] = z;
        sH2[0][tid][0] = z; sH2[0][tid][1] = z;
    }
    __syncthreads();

    const ulonglong2* __restrict__ w1p = ((const ulonglong2*)g_w1) + tid;
    const ulonglong2* __restrict__ w2p = ((const ulonglong2*)g_w2) + tid * 2;

    int cur = 0;
    u64 aif[BC], ago[BC];

    for (int t = 0; t < TT; ++t) {
        const int nxt = cur ^ 1;

        // ================= layer 1 =================
#pragma unroll
        for (int b = 0; b < BC; ++b) {
            u64 xb = bc2(sx[b][t]);
            aif[b] = b0_if; fma2(aif[b], xb, wx_if);
            ago[b] = b0_go; fma2(ago[b], xb, wx_go);
        }
#pragma unroll 8
        for (int k = 0; k < HH; ++k) {
            ulonglong2 wv = w1p[k * HH];           // (wi,wf),(wg,wo)
            ulonglong2 ha = sH1[cur][k][0];        // (h0,h0),(h1,h1)
            ulonglong2 hb = sH1[cur][k][1];        // (h2,h2),(h3,h3)
            fma2(aif[0], ha.x, wv.x); fma2(ago[0], ha.x, wv.y);
            fma2(aif[1], ha.y, wv.x); fma2(ago[1], ha.y, wv.y);
            fma2(aif[2], hb.x, wv.x); fma2(ago[2], hb.x, wv.y);
            fma2(aif[3], hb.y, wv.x); fma2(ago[3], hb.y, wv.y);
        }
        {
            float hn[BC];
#pragma unroll
            for (int b = 0; b < BC; ++b) {
                float ai, af, ag, ao;
                up2(aif[b], ai, af); up2(ago[b], ag, ao);
                float I = sigf(ai), F = sigf(af);
                float G = tanhfast(ag), O = sigf(ao);
                c1[b] = F * c1[b] + I * G;
                hn[b] = O * tanhfast(c1[b]);
            }
            ulonglong2 pa, pb;
            pa.x = bc2(hn[0]); pa.y = bc2(hn[1]);
            pb.x = bc2(hn[2]); pb.y = bc2(hn[3]);
            sH1[nxt][tid][0] = pa;
            sH1[nxt][tid][1] = pb;
        }
        __syncthreads();   // new h1 visible

        // ================= layer 2 =================
#pragma unroll
        for (int b = 0; b < BC; ++b) { aif[b] = b1_if; ago[b] = b1_go; }
#pragma unroll 4
        for (int k = 0; k < HH; ++k) {
            ulonglong2 wA = w2p[k * HH * 2];       // w_ih1 gates
            ulonglong2 wB = w2p[k * HH * 2 + 1];   // w_hh1 gates
            ulonglong2 pa = sH1[nxt][k][0];
            ulonglong2 pb = sH1[nxt][k][1];
            ulonglong2 qa = sH2[cur][k][0];
            ulonglong2 qb = sH2[cur][k][1];
            fma2(aif[0], pa.x, wA.x); fma2(ago[0], pa.x, wA.y);
            fma2(aif[0], qa.x, wB.x); fma2(ago[0], qa.x, wB.y);
            fma2(aif[1], pa.y, wA.x); fma2(ago[1], pa.y, wA.y);
            fma2(aif[1], qa.y, wB.x); fma2(ago[1], qa.y, wB.y);
            fma2(aif[2], pb.x, wA.x); fma2(ago[2], pb.x, wA.y);
            fma2(aif[2], qb.x, wB.x); fma2(ago[2], qb.x, wB.y);
            fma2(aif[3], pb.y, wA.x); fma2(ago[3], pb.y, wA.y);
            fma2(aif[3], qb.y, wB.x); fma2(ago[3], qb.y, wB.y);
        }
        {
            float hn[BC];
#pragma unroll
            for (int b = 0; b < BC; ++b) {
                float ai, af, ag, ao;
                up2(aif[b], ai, af); up2(ago[b], ag, ao);
                float I = sigf(ai), F = sigf(af);
                float G = tanhfast(ag), O = sigf(ao);
                c2[b] = F * c2[b] + I * G;
                hn[b] = O * tanhfast(c2[b]);
            }
            ulonglong2 pa, pb;
            pa.x = bc2(hn[0]); pa.y = bc2(hn[1]);
            pb.x = bc2(hn[2]); pb.y = bc2(hn[3]);
            sH2[nxt][tid][0] = pa;
            sH2[nxt][tid][1] = pb;
        }
        __syncthreads();   // new h2 visible, old buffers free
        cur = nxt;
    }

    // ---------------- linear head on final h2 (56 dots per CTA) -----------
    // final h2 lives in sH2[cur]; value for (k, b) is the low float of
    // u64 element ((k*2 + b/2) pair, lane b&1) -> flat float index (k*4+b)*2
    const float* __restrict__ h2f = (const float*)&sH2[cur][0][0];
    const int warp = tid >> 5, lane = tid & 31;
    for (int pair = warp; pair < BC * PP; pair += NT / 32) {
        int b = pair / PP, p = pair % PP;
        float s = 0.f;
        for (int k = lane; k < HH; k += 32)
            s += h2f[(k * 4 + b) * 2] * w_lin[p * HH + k];
#pragma unroll
        for (int off = 16; off > 0; off >>= 1)
            s += __shfl_xor_sync(0xffffffff, s, off);
        if (lane == 0)
            out[(b0 + b) * PP + p] = s + b_lin[p];
    }
}

// ---------------- launch --------------------------------------------------
extern "C" void kernel_launch(void* const* d_in, const int* in_sizes, int n_in,
                              void* d_out, int out_size)
{
    const float* x     = (const float*)d_in[0];
    const float* w_ih0 = (const float*)d_in[1];
    const float* w_hh0 = (const float*)d_in[2];
    const float* b_ih0 = (const float*)d_in[3];
    const float* b_hh0 = (const float*)d_in[4];
    const float* w_ih1 = (const float*)d_in[5];
    const float* w_hh1 = (const float*)d_in[6];
    const float* b_ih1 = (const float*)d_in[7];
    const float* b_hh1 = (const float*)d_in[8];
    const float* w_lin = (const float*)d_in[9];
    const float* b_lin = (const float*)d_in[10];
    float* out = (float*)d_out;

    prep_kernel<<<256, 256>>>(w_ih0, w_hh0, b_ih0, b_hh0,
                              w_ih1, w_hh1, b_ih1, b_hh1);
    lstm_kernel<<<NCTA, NT>>>(x, w_lin, b_lin, out);
}

// round 8
// speedup vs baseline: 1.5215x; 1.0413x over previous
#include <cuda_runtime.h>
#include <cstdint>
#include <math.h>

typedef unsigned long long u64;

// Problem constants
#define BB 512   // batch
#define TT 256   // seq len
#define HH 256   // hidden
#define PP 14    // predict dim

#define BC 8                  // batch per cluster pair
#define NCTA 128              // 64 groups x 2 CTAs (cluster pairs)
#define NT  256               // threads: 2 per hidden-unit-half (unit, batch-half)

// ---------------- scratch (device globals; allocation-free) ----------------
//   g_w1[(k*HH + h)*4 + q] = w_hh0[(q*HH + h)*HH + k]   (q: 0=i,1=f,2=g,3=o)
__device__ __align__(16) float g_w1[HH * HH * 4];
//   g_w2[((k*HH + h)*2 + m)*4 + q], m=0 -> w_ih1, m=1 -> w_hh1
__device__ __align__(16) float g_w2[HH * HH * 8];
__device__ __align__(16) float g_b0p[HH * 4];
__device__ __align__(16) float g_b1p[HH * 4];
__device__ __align__(16) float g_wxp[HH * 4];

// ---------------- prep: transpose + pack ----------------------------------
__global__ void prep_kernel(const float* __restrict__ w_ih0,
                            const float* __restrict__ w_hh0,
                            const float* __restrict__ b_ih0,
                            const float* __restrict__ b_hh0,
                            const float* __restrict__ w_ih1,
                            const float* __restrict__ w_hh1,
                            const float* __restrict__ b_ih1,
                            const float* __restrict__ b_hh1)
{
    int tid = blockIdx.x * blockDim.x + threadIdx.x;
    int nthr = gridDim.x * blockDim.x;
    for (int i = tid; i < HH * HH * 4; i += nthr) {
        int q = i & 3;
        int h = (i >> 2) & (HH - 1);
        int k = i >> 10;
        int src = (q * HH + h) * HH + k;
        g_w1[i] = w_hh0[src];
        g_w2[((k * HH + h) * 2 + 0) * 4 + q] = w_ih1[src];
        g_w2[((k * HH + h) * 2 + 1) * 4 + q] = w_hh1[src];
    }
    for (int i = tid; i < HH * 4; i += nthr) {
        int q = i & 3;
        int h = i >> 2;
        int g = q * HH + h;
        g_b0p[i] = b_ih0[g] + b_hh0[g];
        g_b1p[i] = b_ih1[g] + b_hh1[g];
        g_wxp[i] = w_ih0[g];
    }
}

// ---------------- f32x2 helpers (Blackwell packed fp32 FMA) ---------------
__device__ __forceinline__ u64 pack2(float lo, float hi) {
    u64 r;
    asm("mov.b64 %0, {%1, %2};" : "=l"(r) : "f"(lo), "f"(hi));
    return r;
}
__device__ __forceinline__ u64 bc2(float v) { return pack2(v, v); }
__device__ __forceinline__ void up2(u64 v, float& lo, float& hi) {
    asm("mov.b64 {%0, %1}, %2;" : "=f"(lo), "=f"(hi) : "l"(v));
}
__device__ __forceinline__ void fma2(u64& d, u64 a, u64 b) {
    asm("fma.rn.f32x2 %0, %1, %2, %0;" : "+l"(d) : "l"(a), "l"(b));
}

__device__ __forceinline__ float sigf(float x) {
    return __fdividef(1.0f, 1.0f + __expf(-x));
}
__device__ __forceinline__ float tanhfast(float x) {
    float e = __expf(2.0f * x);
    return 1.0f - __fdividef(2.0f, e + 1.0f);
}

// ---------------- cluster helpers -----------------------------------------
__device__ __forceinline__ uint32_t smem_u32(const void* p) {
    uint32_t a;
    asm("{ .reg .u64 t; cvta.to.shared.u64 t, %1; cvt.u32.u64 %0, t; }"
        : "=r"(a) : "l"(p));
    return a;
}
__device__ __forceinline__ uint32_t mapa_u32(uint32_t a, uint32_t r) {
    uint32_t d;
    asm("mapa.shared::cluster.u32 %0, %1, %2;" : "=r"(d) : "r"(a), "r"(r));
    return d;
}
__device__ __forceinline__ void st_cl64(uint32_t addr, u64 v) {
    asm volatile("st.shared::cluster.b64 [%0], %1;" :: "r"(addr), "l"(v) : "memory");
}
#define CLUSTER_SYNC() do { \
    asm volatile("barrier.cluster.arrive.aligned;" ::: "memory"); \
    asm volatile("barrier.cluster.wait.aligned;" ::: "memory"); \
} while (0)

// ---------------- smem layout (dynamic, 72 KB) -----------------------------
// sH1: [2][256 units][4 x ulonglong2]  (8 batches, value-duplicated) 32 KB
// sH2: same, 32 KB
// sx : [8][256] floats, 8 KB
#define SM_H1 0
#define SM_H2 32768
#define SM_X  65536
#define SM_TOTAL 73728

// ---------------- fused 2-layer LSTM + head -------------------------------
__global__ __launch_bounds__(NT, 1) __cluster_dims__(2, 1, 1)
void lstm_kernel(const float* __restrict__ x,      // [B, T, 1]
                 const float* __restrict__ w_lin,  // [P, H]
                 const float* __restrict__ b_lin,  // [P]
                 float* __restrict__ out)          // [B, P]
{
    extern __shared__ __align__(16) char smem[];
    ulonglong2* sH1 = (ulonglong2*)(smem + SM_H1);   // [2*256*4]
    ulonglong2* sH2 = (ulonglong2*)(smem + SM_H2);
    float*      sx  = (float*)(smem + SM_X);         // [8*256]

    const int tid = threadIdx.x;
    uint32_t rank;
    asm("mov.u32 %0, %%cluster_ctarank;" : "=r"(rank));
    const int grp = blockIdx.x >> 1;
    const int b0  = grp * BC;
    const int ul  = tid >> 1;                    // local unit 0..127
    const int u   = (int)rank * 128 + ul;        // global hidden unit
    const int j0  = (tid & 1) * 2;               // ulonglong2 slot for my 4 batches
    const int bh  = (tid & 1) * 4;               // batch offset 0 or 4

    const uint32_t my_base   = smem_u32(smem);
    const uint32_t peer_base = mapa_u32(my_base, rank ^ 1);

    // stage input slice [8 batches][256 steps]
    for (int i = tid; i < BC * TT; i += NT)
        sx[i] = x[(b0 + i / TT) * TT + (i % TT)];

    // zero state buffers (buf 0 of each)
    {
        ulonglong2 z; z.x = 0ull; z.y = 0ull;
        for (int i = tid; i < 1024; i += NT) { sH1[i] = z; sH2[i] = z; }
    }

    // per-unit constants (registers)
    float4 wx  = ((const float4*)g_wxp)[u];
    float4 bz0 = ((const float4*)g_b0p)[u];
    float4 bz1 = ((const float4*)g_b1p)[u];
    const u64 wx_if = pack2(wx.x, wx.y),   wx_go = pack2(wx.z, wx.w);
    const u64 b0_if = pack2(bz0.x, bz0.y), b0_go = pack2(bz0.z, bz0.w);
    const u64 b1_if = pack2(bz1.x, bz1.y), b1_go = pack2(bz1.z, bz1.w);

    float c1[4] = {0.f, 0.f, 0.f, 0.f};
    float c2[4] = {0.f, 0.f, 0.f, 0.f};
    __syncthreads();
    CLUSTER_SYNC();    // both CTAs' buffers zeroed before any peer writes

    const ulonglong2* __restrict__ w1p = (const ulonglong2*)g_w1;
    const ulonglong2* __restrict__ w2p = (const ulonglong2*)g_w2;

    int cur = 0;
    u64 aif[4], ago[4];

    for (int t = 0; t < TT; ++t) {
        const int nxt = cur ^ 1;

        // ================= layer 1 (this CTA: gates for its 128 units) ======
#pragma unroll
        for (int b = 0; b < 4; ++b) {
            u64 xb = bc2(sx[(bh + b) * TT + t]);
            aif[b] = b0_if; fma2(aif[b], xb, wx_if);
            ago[b] = b0_go; fma2(ago[b], xb, wx_go);
        }
#pragma unroll 8
        for (int k = 0; k < HH; ++k) {
            ulonglong2 wv = w1p[k * HH + u];                 // (wi,wf),(wg,wo)
            ulonglong2 ha = sH1[cur * 1024 + k * 4 + j0];    // my batches 0,1
            ulonglong2 hb = sH1[cur * 1024 + k * 4 + j0 + 1];// my batches 2,3
            fma2(aif[0], ha.x, wv.x); fma2(ago[0], ha.x, wv.y);
            fma2(aif[1], ha.y, wv.x); fma2(ago[1], ha.y, wv.y);
            fma2(aif[2], hb.x, wv.x); fma2(ago[2], hb.x, wv.y);
            fma2(aif[3], hb.y, wv.x); fma2(ago[3], hb.y, wv.y);
        }
        {
            u64 hd[4];
#pragma unroll
            for (int b = 0; b < 4; ++b) {
                float ai, af, ag, ao;
                up2(aif[b], ai, af); up2(ago[b], ag, ao);
                float I = sigf(ai), F = sigf(af);
                float G = tanhfast(ag), O = sigf(ao);
                c1[b] = F * c1[b] + I * G;
                hd[b] = bc2(O * tanhfast(c1[b]));
            }
            int idx = nxt * 1024 + u * 4 + j0;
            ulonglong2 p; p.x = hd[0]; p.y = hd[1];
            ulonglong2 q; q.x = hd[2]; q.y = hd[3];
            sH1[idx] = p; sH1[idx + 1] = q;                  // local copy
            uint32_t ra = peer_base + SM_H1 + (uint32_t)idx * 16u;
            st_cl64(ra,      hd[0]); st_cl64(ra + 8,  hd[1]); // peer copy
            st_cl64(ra + 16, hd[2]); st_cl64(ra + 24, hd[3]);
        }
        CLUSTER_SYNC();    // both halves of new h1 visible everywhere

        // ================= layer 2 ==========================================
#pragma unroll
        for (int b = 0; b < 4; ++b) { aif[b] = b1_if; ago[b] = b1_go; }
#pragma unroll 4
        for (int k = 0; k < HH; ++k) {
            ulonglong2 wA = w2p[(k * HH + u) * 2];           // w_ih1 gates
            ulonglong2 wB = w2p[(k * HH + u) * 2 + 1];       // w_hh1 gates
            ulonglong2 pa = sH1[nxt * 1024 + k * 4 + j0];
            ulonglong2 pb = sH1[nxt * 1024 + k * 4 + j0 + 1];
            ulonglong2 qa = sH2[cur * 1024 + k * 4 + j0];
            ulonglong2 qb = sH2[cur * 1024 + k * 4 + j0 + 1];
            fma2(aif[0], pa.x, wA.x); fma2(ago[0], pa.x, wA.y);
            fma2(aif[0], qa.x, wB.x); fma2(ago[0], qa.x, wB.y);
            fma2(aif[1], pa.y, wA.x); fma2(ago[1], pa.y, wA.y);
            fma2(aif[1], qa.y, wB.x); fma2(ago[1], qa.y, wB.y);
            fma2(aif[2], pb.x, wA.x); fma2(ago[2], pb.x, wA.y);
            fma2(aif[2], qb.x, wB.x); fma2(ago[2], qb.x, wB.y);
            fma2(aif[3], pb.y, wA.x); fma2(ago[3], pb.y, wA.y);
            fma2(aif[3], qb.y, wB.x); fma2(ago[3], qb.y, wB.y);
        }
        {
            u64 hd[4];
#pragma unroll
            for (int b = 0; b < 4; ++b) {
                float ai, af, ag, ao;
                up2(aif[b], ai, af); up2(ago[b], ag, ao);
                float I = sigf(ai), F = sigf(af);
                float G = tanhfast(ag), O = sigf(ao);
                c2[b] = F * c2[b] + I * G;
                hd[b] = bc2(O * tanhfast(c2[b]));
            }
            int idx = nxt * 1024 + u * 4 + j0;
            ulonglong2 p; p.x = hd[0]; p.y = hd[1];
            ulonglong2 q; q.x = hd[2]; q.y = hd[3];
            sH2[idx] = p; sH2[idx + 1] = q;
            uint32_t ra = peer_base + SM_H2 + (uint32_t)idx * 16u;
            st_cl64(ra,      hd[0]); st_cl64(ra + 8,  hd[1]);
            st_cl64(ra + 16, hd[2]); st_cl64(ra + 24, hd[3]);
        }
        CLUSTER_SYNC();
        cur = nxt;
    }

    // ---------------- linear head: each CTA outputs 4 of the 8 batches -----
    const float* __restrict__ h2f = (const float*)&sH2[cur * 1024];
    const int warp = tid >> 5, lane = tid & 31;
    const int bbase = (int)rank * 4;
    for (int pair = warp; pair < 4 * PP; pair += NT / 32) {
        int b = bbase + pair / PP, p = pair % PP;
        float s = 0.f;
        for (int k = lane; k < HH; k += 32)
            s += h2f[k * 16 + (b >> 1) * 4 + (b & 1) * 2] * w_lin[p * HH + k];
#pragma unroll
        for (int off = 16; off > 0; off >>= 1)
            s += __shfl_xor_sync(0xffffffff, s, off);
        if (lane == 0)
            out[(b0 + b) * PP + p] = s + b_lin[p];
    }
    CLUSTER_SYNC();    // no CTA exits while peer stores may be in flight
}

// ---------------- launch --------------------------------------------------
extern "C" void kernel_launch(void* const* d_in, const int* in_sizes, int n_in,
                              void* d_out, int out_size)
{
    const float* x     = (const float*)d_in[0];
    const float* w_ih0 = (const float*)d_in[1];
    const float* w_hh0 = (const float*)d_in[2];
    const float* b_ih0 = (const float*)d_in[3];
    const float* b_hh0 = (const float*)d_in[4];
    const float* w_ih1 = (const float*)d_in[5];
    const float* w_hh1 = (const float*)d_in[6];
    const float* b_ih1 = (const float*)d_in[7];
    const float* b_hh1 = (const float*)d_in[8];
    const float* w_lin = (const float*)d_in[9];
    const float* b_lin = (const float*)d_in[10];
    float* out = (float*)d_out;

    cudaFuncSetAttribute(lstm_kernel,
                         cudaFuncAttributeMaxDynamicSharedMemorySize, SM_TOTAL);

    prep_kernel<<<256, 256>>>(w_ih0, w_hh0, b_ih0, b_hh0,
                              w_ih1, w_hh1, b_ih1, b_hh1);
    lstm_kernel<<<NCTA, NT, SM_TOTAL>>>(x, w_lin, b_lin, out);
}